// round 15
// baseline (speedup 1.0000x reference)
#include <cuda_runtime.h>
#include <cstdint>

// EConv: out[dst] += x[src] * edge_attr[e]  over 1M edges, d=64
// Probe: EPT=2 (lower regs -> higher occupancy) on the champion schedule
// (edge-order, red.global.add.v4.f32, 32-bit byte offsets, block=256).
// d_in[0]: x          float32 [100000*64]
// d_in[1]: edge_index int32   [2*1000000]  (row 0 = dst, row 1 = src)
// d_in[2]: edge_attr  float32 [1000000*64]
// d_out:   float32 [100000*64]

#define ROW_BYTES 256u   // 64 floats
#define EPT 2            // edges per thread

__global__ __launch_bounds__(256) void econv_kernel(
    const char* __restrict__ x_b,         // x base (bytes)
    const int* __restrict__ dst_idx,      // [E]
    const int* __restrict__ src_idx,      // [E]
    const char* __restrict__ attr_b,      // edge_attr base (bytes)
    char* __restrict__ out_b,             // out base (bytes)
    int E)
{
    int t = blockIdx.x * blockDim.x + threadIdx.x;
    int g = t >> 4;               // edge-group id
    unsigned cb = (t & 15) * 16u; // byte offset of this thread's float4 chunk
    int e0 = g * EPT;
    if (e0 >= E) return;

    // One LDG.64 each for 2 src + 2 dst indices (e0 is 2-aligned)
    int2 s2 = __ldcs((const int2*)(src_idx + e0));
    int2 d2 = __ldcs((const int2*)(dst_idx + e0));
    int src[EPT] = {s2.x, s2.y};
    int dst[EPT] = {d2.x, d2.y};

    // Front-batch the 4 data loads (32-bit offsets)
    float4 xv[EPT], av[EPT];
    unsigned ab = (unsigned)e0 * ROW_BYTES + cb;
#pragma unroll
    for (int i = 0; i < EPT; i++) {
        xv[i] = __ldg((const float4*)(x_b + ((unsigned)src[i] * ROW_BYTES + cb)));
        av[i] = __ldcs((const float4*)(attr_b + ab + (unsigned)i * ROW_BYTES));
    }

#pragma unroll
    for (int i = 0; i < EPT; i++) {
        av[i].x *= xv[i].x;
        av[i].y *= xv[i].y;
        av[i].z *= xv[i].z;
        av[i].w *= xv[i].w;
        char* p = out_b + ((unsigned)dst[i] * ROW_BYTES + cb);
        asm volatile(
            "red.global.add.v4.f32 [%0], {%1, %2, %3, %4};"
            :: "l"(p), "f"(av[i].x), "f"(av[i].y), "f"(av[i].z), "f"(av[i].w)
            : "memory");
    }
}

extern "C" void kernel_launch(void* const* d_in, const int* in_sizes, int n_in,
                              void* d_out, int out_size) {
    const char* x_b = (const char*)d_in[0];
    const int* edge_index = (const int*)d_in[1];
    const char* attr_b = (const char*)d_in[2];

    int E = in_sizes[1] / 2;                 // 1,000,000
    const int* dst_idx = edge_index;         // row 0
    const int* src_idx = edge_index + E;     // row 1

    // Zero the output (graph-capturable memset node)
    cudaMemsetAsync(d_out, 0, (size_t)out_size * sizeof(float));

    long long total = (long long)(E / EPT) * 16;  // 8M threads
    int blocks = (int)((total + 255) / 256);
    econv_kernel<<<blocks, 256>>>(
        x_b, dst_idx, src_idx, attr_b, (char*)d_out, E);
}

// round 16
// speedup vs baseline: 1.0208x; 1.0208x over previous
#include <cuda_runtime.h>
#include <cstdint>

// EConv: out[dst] += x[src] * edge_attr[e]  over 1M edges, d=64
// FINAL (champion, measured 65.98us total / 63.2us main):
//   - edge-order processing: keeps the 256MB edge_attr stream sequential
//   - 16 threads per edge-group, each owning one float4 chunk of the 64-wide row
//   - EPT=4 front-batched loads for MLP; __ldcs on one-touch streams so the
//     25.6MB x table stays L2-resident
//   - red.global.add.v4.f32 (no-return vector reduction) for scatter-add
//   - 32-bit byte-offset addressing (regs=34, occ ~60%)
//   - memset node for output zeroing (true serial dependency per graph replay)
// Floor analysis: 776MB compulsory L2 traffic / ~12.3TB/s practical LTS cap
// = ~63us main; verified binding via occupancy probe (EPT=2: occ 84%, slower).
// d_in[0]: x          float32 [100000*64]
// d_in[1]: edge_index int32   [2*1000000]  (row 0 = dst, row 1 = src)
// d_in[2]: edge_attr  float32 [1000000*64]
// d_out:   float32 [100000*64]

#define ROW_BYTES 256u   // 64 floats
#define EPT 4            // edges per thread

__global__ __launch_bounds__(256) void econv_kernel(
    const char* __restrict__ x_b,         // x base (bytes)
    const int* __restrict__ dst_idx,      // [E]
    const int* __restrict__ src_idx,      // [E]
    const char* __restrict__ attr_b,      // edge_attr base (bytes)
    char* __restrict__ out_b,             // out base (bytes)
    int E)
{
    int t = blockIdx.x * blockDim.x + threadIdx.x;
    int g = t >> 4;               // edge-group id
    unsigned cb = (t & 15) * 16u; // byte offset of this thread's float4 chunk
    int e0 = g * EPT;
    if (e0 >= E) return;

    // One LDG.128 each for 4 src + 4 dst indices (e0 is 4-aligned)
    int4 s4 = __ldcs((const int4*)(src_idx + e0));
    int4 d4 = __ldcs((const int4*)(dst_idx + e0));
    int src[EPT] = {s4.x, s4.y, s4.z, s4.w};
    int dst[EPT] = {d4.x, d4.y, d4.z, d4.w};

    // Front-batch the 8 data loads (32-bit offsets: all arrays < 4GB).
    // x: default caching (L2-resident). attr: evict-first stream.
    float4 xv[EPT], av[EPT];
    unsigned ab = (unsigned)e0 * ROW_BYTES + cb;
#pragma unroll
    for (int i = 0; i < EPT; i++) {
        xv[i] = __ldg((const float4*)(x_b + ((unsigned)src[i] * ROW_BYTES + cb)));
        av[i] = __ldcs((const float4*)(attr_b + ab + (unsigned)i * ROW_BYTES));
    }

#pragma unroll
    for (int i = 0; i < EPT; i++) {
        av[i].x *= xv[i].x;
        av[i].y *= xv[i].y;
        av[i].z *= xv[i].z;
        av[i].w *= xv[i].w;
        char* p = out_b + ((unsigned)dst[i] * ROW_BYTES + cb);
        asm volatile(
            "red.global.add.v4.f32 [%0], {%1, %2, %3, %4};"
            :: "l"(p), "f"(av[i].x), "f"(av[i].y), "f"(av[i].z), "f"(av[i].w)
            : "memory");
    }
}

extern "C" void kernel_launch(void* const* d_in, const int* in_sizes, int n_in,
                              void* d_out, int out_size) {
    const char* x_b = (const char*)d_in[0];
    const int* edge_index = (const int*)d_in[1];
    const char* attr_b = (const char*)d_in[2];

    int E = in_sizes[1] / 2;                 // 1,000,000
    const int* dst_idx = edge_index;         // row 0
    const int* src_idx = edge_index + E;     // row 1

    // Zero the output (graph-capturable memset node; required every replay)
    cudaMemsetAsync(d_out, 0, (size_t)out_size * sizeof(float));

    long long total = (long long)(E / EPT) * 16;  // 4M threads
    int blocks = (int)((total + 255) / 256);
    econv_kernel<<<blocks, 256>>>(
        x_b, dst_idx, src_idx, attr_b, (char*)d_out, E);
}